// round 6
// baseline (speedup 1.0000x reference)
#include <cuda_runtime.h>
#include <cstdint>
#include <cstddef>

#define D_OUT 64
#define D_IN  256
#define CAP   2048
#define MAXNA 16384
#define MAXIT 10          // per-thread uint4 iterations: covers N <= 10240 (words)

// scratch for proj = anchor @ wt  (allocation-free rule: __device__ global)
__device__ float g_proj[(size_t)MAXNA * D_OUT];

// ---------------------------------------------------------------------------
// proj_kernel: proj[r][c] = sum_k anchor[r][k] * wt[k][c]
// 32 rows/block, 256 threads, k tiled in 4 chunks of 64.
// ---------------------------------------------------------------------------
__global__ __launch_bounds__(256) void proj_kernel(const float* __restrict__ anchor,
                                                   const float* __restrict__ wt,
                                                   int Na) {
    __shared__ float4 s_wt4[64 * 16];   // [k][colgroup]  16 KB
    __shared__ float4 s_an4[32 * 16];   // [row][kgroup]   8 KB
    float* s_an = (float*)s_an4;

    const int tid  = threadIdx.x;
    const int row0 = blockIdx.x * 32;
    const int cg   = tid & 15;
    const int rg   = tid >> 4;
    const int r0   = rg * 2, r1 = rg * 2 + 1;

    const float4* wt4 = (const float4*)wt;       // [256][16] float4
    const float4* an4 = (const float4*)anchor;   // [Na][64]  float4

    float4 acc0 = {0.f, 0.f, 0.f, 0.f};
    float4 acc1 = {0.f, 0.f, 0.f, 0.f};

    for (int kt = 0; kt < D_IN / 64; kt++) {
        #pragma unroll
        for (int i = 0; i < 4; i++) {
            int g = tid + i * 256;
            s_wt4[g] = wt4[(size_t)(kt * 64 + (g >> 4)) * 16 + (g & 15)];
        }
        #pragma unroll
        for (int i = 0; i < 2; i++) {
            int g = tid + i * 256;
            int rr = g >> 4, k4 = g & 15;
            float4 av = {0.f, 0.f, 0.f, 0.f};
            if (row0 + rr < Na)
                av = an4[(size_t)(row0 + rr) * (D_IN / 4) + kt * 16 + k4];
            s_an4[rr * 16 + k4] = av;
        }
        __syncthreads();
        #pragma unroll
        for (int k = 0; k < 64; k++) {
            float4 wv = s_wt4[k * 16 + cg];
            float a0 = s_an[r0 * 64 + k];
            float a1 = s_an[r1 * 64 + k];
            acc0.x += a0 * wv.x; acc0.y += a0 * wv.y;
            acc0.z += a0 * wv.z; acc0.w += a0 * wv.w;
            acc1.x += a1 * wv.x; acc1.y += a1 * wv.y;
            acc1.z += a1 * wv.z; acc1.w += a1 * wv.w;
        }
        __syncthreads();
    }
    if (row0 + r0 < Na) ((float4*)g_proj)[(size_t)(row0 + r0) * 16 + cg] = acc0;
    if (row0 + r1 < Na) ((float4*)g_proj)[(size_t)(row0 + r1) * 16 + cg] = acc1;
}

// ---------------------------------------------------------------------------
// attn_kernel: one block per anchor row.
// adjs is treated as 32-bit WORDS (one per logical bool element): nonzero word
// == True. Correct whether the harness canonicalized bool -> int32 (0/1) or
// bool -> float32 (0.0f/1.0f, bits 0x3F800000).
// Masked entries are exactly 0 after softmax (exp underflow at NEG_INF/T),
// so the sparse formulation is exact.
// ---------------------------------------------------------------------------
__global__ __launch_bounds__(256) void attn_kernel(const float* __restrict__ x,
                                                   const float* __restrict__ weight,
                                                   const unsigned int* __restrict__ adjs,
                                                   const int* __restrict__ idxp,
                                                   float* __restrict__ out,
                                                   int N, int Na) {
    __shared__ int    s_idx[CAP];
    __shared__ float  s_sc[CAP];
    __shared__ float4 s_proj4[16];
    __shared__ int    s_woff[9];
    __shared__ float  s_red[8];
    __shared__ float  s_bcast[2];
    __shared__ float  s_acc[256];

    const int i    = blockIdx.x;
    const int tid  = threadIdx.x;
    const int lane = tid & 31;
    const int wrp  = tid >> 5;

    const int   idx = *idxp;
    const float wsc = weight[idx];
    const unsigned int* adj = adjs + ((size_t)idx * Na + i) * (size_t)N;  // word ptr

    if (tid < 16) s_proj4[tid] = ((const float4*)g_proj)[(size_t)i * 16 + tid];

    const int  W4   = N >> 2;            // uint4 chunks (4 words each)
    const int  tail = N & 3;             // leftover words
    const bool vec  = ((((uintptr_t)adj) & 15) == 0) && (W4 <= 256 * MAXIT);

    // ---- pass 1: count nonzero words (cache uint4 vectors in registers) ----
    int   cnt_t = 0;
    uint4 v[MAXIT];
    unsigned int tw = 0u;

    if (vec) {
        const uint4* a4 = (const uint4*)adj;
        #pragma unroll
        for (int it = 0; it < MAXIT; it++) {
            int q = tid + (it << 8);
            uint4 t = {0u, 0u, 0u, 0u};
            if (q < W4) t = a4[q];
            v[it] = t;
            cnt_t += (int)(t.x != 0u) + (int)(t.y != 0u)
                   + (int)(t.z != 0u) + (int)(t.w != 0u);
        }
        if (tid < tail) { tw = adj[(W4 << 2) + tid]; cnt_t += (tw != 0u); }
    } else {
        for (int j = tid; j < N; j += 256) cnt_t += (adj[j] != 0u);
    }

    // ---- block exclusive scan over per-thread counts (deterministic) ----
    int incl = cnt_t;
    #pragma unroll
    for (int o = 1; o < 32; o <<= 1) {
        int p = __shfl_up_sync(0xffffffffu, incl, o);
        if (lane >= o) incl += p;
    }
    if (lane == 31) s_woff[wrp] = incl;
    __syncthreads();
    if (tid == 0) {
        int run = 0;
        #pragma unroll
        for (int k2 = 0; k2 < 8; k2++) { int c2 = s_woff[k2]; s_woff[k2] = run; run += c2; }
        s_woff[8] = run;
    }
    __syncthreads();
    int off = s_woff[wrp] + incl - cnt_t;
    const int cnt = min(s_woff[8], CAP);

    // ---- pass 2: emit neighbor indices from registers ----
    if (vec) {
        #pragma unroll
        for (int it = 0; it < MAXIT; it++) {
            int q = tid + (it << 8);
            if (q < W4) {
                int j = q << 2;
                uint4 t = v[it];
                if (t.x) { if (off < CAP) s_idx[off] = j + 0; off++; }
                if (t.y) { if (off < CAP) s_idx[off] = j + 1; off++; }
                if (t.z) { if (off < CAP) s_idx[off] = j + 2; off++; }
                if (t.w) { if (off < CAP) s_idx[off] = j + 3; off++; }
            }
        }
        if (tid < tail && tw) { if (off < CAP) s_idx[off] = (W4 << 2) + tid; off++; }
    } else {
        for (int j = tid; j < N; j += 256) {
            if (adj[j] != 0u) { if (off < CAP) s_idx[off] = j; off++; }
        }
    }
    __syncthreads();

    if (cnt > 0) {
        // ---- scores: 16 threads per neighbor, float4 partial dots ----
        const int g = tid >> 4, l16 = tid & 15;
        const unsigned gmask = 0xFFFFu << (lane & 16);
        for (int n = g; n < cnt; n += 16) {
            const float4* xr = (const float4*)(x + (size_t)s_idx[n] * D_OUT);
            float4 xv = xr[l16];
            float4 pv = s_proj4[l16];
            float p = xv.x * pv.x + xv.y * pv.y + xv.z * pv.z + xv.w * pv.w;
            p += __shfl_down_sync(gmask, p, 8);
            p += __shfl_down_sync(gmask, p, 4);
            p += __shfl_down_sync(gmask, p, 2);
            p += __shfl_down_sync(gmask, p, 1);
            if (l16 == 0) s_sc[n] = p;
        }
        __syncthreads();

        // ---- softmax over cnt scores ----
        float m = -3.4e38f;
        for (int n = tid; n < cnt; n += 256) m = fmaxf(m, s_sc[n]);
        #pragma unroll
        for (int o = 16; o; o >>= 1) m = fmaxf(m, __shfl_xor_sync(0xffffffffu, m, o));
        if (lane == 0) s_red[wrp] = m;
        __syncthreads();
        if (tid == 0) {
            float mm = s_red[0];
            #pragma unroll
            for (int k2 = 1; k2 < 8; k2++) mm = fmaxf(mm, s_red[k2]);
            s_bcast[0] = mm;
        }
        __syncthreads();
        m = s_bcast[0];

        const float invT = 1.0f / 0.07f;
        float ls = 0.f;
        for (int n = tid; n < cnt; n += 256) {
            float e = __expf((s_sc[n] - m) * invT);
            s_sc[n] = e;
            ls += e;
        }
        #pragma unroll
        for (int o = 16; o; o >>= 1) ls += __shfl_xor_sync(0xffffffffu, ls, o);
        if (lane == 0) s_red[wrp] = ls;
        __syncthreads();
        if (tid == 0) {
            float ss = 0.f;
            #pragma unroll
            for (int k2 = 0; k2 < 8; k2++) ss += s_red[k2];
            s_bcast[1] = ss;
        }
        __syncthreads();
        const float scale = wsc / s_bcast[1];

        // ---- output: out[i][c] = scale * sum_n e_n * x[j_n][c] ----
        const int c = tid & 63, part = tid >> 6;
        float acc = 0.f;
        for (int n = part; n < cnt; n += 4)
            acc += s_sc[n] * x[(size_t)s_idx[n] * D_OUT + c];
        s_acc[tid] = acc;
        __syncthreads();
        if (tid < 64)
            out[(size_t)i * D_OUT + tid] =
                scale * (s_acc[tid] + s_acc[tid + 64] + s_acc[tid + 128] + s_acc[tid + 192]);
    } else {
        // empty adjacency row: reference softmax degenerates to uniform 1/N
        const int c = tid & 63, part = tid >> 6;
        float acc = 0.f;
        for (int j = part; j < N; j += 4) acc += x[(size_t)j * D_OUT + c];
        s_acc[tid] = acc;
        __syncthreads();
        if (tid < 64)
            out[(size_t)i * D_OUT + tid] =
                wsc * (s_acc[tid] + s_acc[tid + 64] + s_acc[tid + 128] + s_acc[tid + 192]) / (float)N;
    }
}

// ---------------------------------------------------------------------------
extern "C" void kernel_launch(void* const* d_in, const int* in_sizes, int n_in,
                              void* d_out, int out_size) {
    const float*        x      = (const float*)d_in[0];
    const float*        weight = (const float*)d_in[1];
    const unsigned int* adjs   = (const unsigned int*)d_in[2];
    const int*          idxp   = (const int*)d_in[3];
    const float*        anchor = (const float*)d_in[4];
    const float*        wt     = (const float*)d_in[5];
    float*              out    = (float*)d_out;

    const int N  = in_sizes[0] / D_OUT;   // 10000
    const int Na = in_sizes[4] / D_IN;    // 10000

    proj_kernel<<<(Na + 31) / 32, 256>>>(anchor, wt, Na);
    attn_kernel<<<Na, 256>>>(x, weight, adjs, idxp, out, N, Na);
}